// round 2
// baseline (speedup 1.0000x reference)
#include <cuda_runtime.h>

#define BATCH 2048
#define SEQ   128
#define F     512
#define NACT  128
#define GN_EPS 1e-5f

// ---------------- scratch (no allocations allowed) ----------------
__device__ float g_p_avg[BATCH * F];
__device__ float g_e_avg[BATCH * F];
__device__ float g_p_embed[BATCH * F];
__device__ int   g_off[NACT + 1];
__device__ int   g_perm[BATCH];

// ---------------- K1: masked mean over seq + GroupNorm(1,1) ----------------
// grid (2048, 2), 128 threads. blockIdx.y: 0 -> precondition, 1 -> effect.
__global__ void k_reduce_gn(const float* __restrict__ pre,
                            const float* __restrict__ eff,
                            const float* __restrict__ gamma,
                            const float* __restrict__ beta)
{
    const int b = blockIdx.x;
    const float* src = (blockIdx.y == 0) ? pre : eff;
    float* dst       = (blockIdx.y == 0) ? g_p_avg : g_e_avg;

    const int t = threadIdx.x;  // 0..127, features 4t..4t+3
    const float4* row = (const float4*)(src + (size_t)b * SEQ * F);

    float4 sum = make_float4(0.f, 0.f, 0.f, 0.f);
    int cx = 0, cy = 0, cz = 0, cw = 0;

    #pragma unroll 8
    for (int s = 0; s < SEQ; s++) {
        float4 v = row[s * (F / 4) + t];
        sum.x += v.x; sum.y += v.y; sum.z += v.z; sum.w += v.w;
        cx += (v.x != 0.0f); cy += (v.y != 0.0f);
        cz += (v.z != 0.0f); cw += (v.w != 0.0f);
    }

    float4 m;
    m.x = sum.x / (float)cx;
    m.y = sum.y / (float)cy;
    m.z = sum.z / (float)cz;
    m.w = sum.w / (float)cw;

    // block-wide mean / var over the 512 per-feature means
    float ls = m.x + m.y + m.z + m.w;
    float lq = m.x * m.x + m.y * m.y + m.z * m.z + m.w * m.w;

    __shared__ float s1[128], s2[128];
    s1[t] = ls; s2[t] = lq;
    __syncthreads();
    #pragma unroll
    for (int o = 64; o > 0; o >>= 1) {
        if (t < o) { s1[t] += s1[t + o]; s2[t] += s2[t + o]; }
        __syncthreads();
    }
    const float mu  = s1[0] * (1.0f / F);
    const float var = s2[0] * (1.0f / F) - mu * mu;
    const float r   = rsqrtf(var + GN_EPS) * gamma[0];
    const float be  = beta[0];

    float4 o4;
    o4.x = (m.x - mu) * r + be;
    o4.y = (m.y - mu) * r + be;
    o4.z = (m.z - mu) * r + be;
    o4.w = (m.w - mu) * r + be;
    ((float4*)(dst + (size_t)b * F))[t] = o4;
}

// ---------------- K2: group batch indices by action ----------------
// single block, 256 threads
__global__ void k_group(const int* __restrict__ action)
{
    __shared__ int s_cnt[NACT];
    __shared__ int s_cur[NACT];
    const int t = threadIdx.x;
    if (t < NACT) s_cnt[t] = 0;
    __syncthreads();
    for (int i = t; i < BATCH; i += 256)
        atomicAdd(&s_cnt[action[i]], 1);
    __syncthreads();
    if (t == 0) {
        int acc = 0;
        for (int a = 0; a < NACT; a++) {
            g_off[a] = acc; s_cur[a] = acc; acc += s_cnt[a];
        }
        g_off[NACT] = acc;
    }
    __syncthreads();
    for (int i = t; i < BATCH; i += 256) {
        int pos = atomicAdd(&s_cur[action[i]], 1);
        g_perm[pos] = i;
    }
}

// ---------------- K3: embed GEMMs  C[b][i] = dot(A[b,:], Wt[i,:]) + bias[i] ---
// grid (F/64, BATCH/64, 2), 256 threads, 64x64 tile, 4x4 microtile, Kt=16
__global__ void k_embed(const float* __restrict__ pw, const float* __restrict__ pb,
                        const float* __restrict__ ew, const float* __restrict__ eb,
                        float* __restrict__ dout)
{
    const float* A; const float* Wt; const float* bias; float* C;
    if (blockIdx.z == 0) { A = g_p_avg; Wt = pw; bias = pb; C = g_p_embed; }
    else                 { A = g_e_avg; Wt = ew; bias = eb; C = dout + (size_t)BATCH * F; }

    const int i0 = blockIdx.x * 64;   // out-dim tile
    const int b0 = blockIdx.y * 64;   // batch tile

    __shared__ float As[16][64];      // [k][b]
    __shared__ float Bs[16][64];      // [k][i]

    const int t  = threadIdx.x;       // 0..255
    const int tx = t & 15;            // i micro-tile
    const int ty = t >> 4;            // b micro-tile

    const int lr = t >> 2;            // loader row 0..63
    const int lk = (t & 3) * 4;       // loader k offset

    float acc[4][4] = {};

    for (int k0 = 0; k0 < F; k0 += 16) {
        float4 av = *(const float4*)(A  + (size_t)(b0 + lr) * F + k0 + lk);
        float4 bv = *(const float4*)(Wt + (size_t)(i0 + lr) * F + k0 + lk);
        As[lk + 0][lr] = av.x; As[lk + 1][lr] = av.y;
        As[lk + 2][lr] = av.z; As[lk + 3][lr] = av.w;
        Bs[lk + 0][lr] = bv.x; Bs[lk + 1][lr] = bv.y;
        Bs[lk + 2][lr] = bv.z; Bs[lk + 3][lr] = bv.w;
        __syncthreads();

        #pragma unroll
        for (int kk = 0; kk < 16; kk++) {
            float4 ra = *(const float4*)&As[kk][ty * 4];
            float4 rb = *(const float4*)&Bs[kk][tx * 4];
            float a_[4] = { ra.x, ra.y, ra.z, ra.w };
            float b_[4] = { rb.x, rb.y, rb.z, rb.w };
            #pragma unroll
            for (int r = 0; r < 4; r++)
                #pragma unroll
                for (int c = 0; c < 4; c++)
                    acc[r][c] += a_[r] * b_[c];
        }
        __syncthreads();
    }

    float bsv[4];
    #pragma unroll
    for (int c = 0; c < 4; c++) bsv[c] = bias[i0 + tx * 4 + c];

    #pragma unroll
    for (int r = 0; r < 4; r++) {
        float4 o;
        o.x = acc[r][0] + bsv[0];
        o.y = acc[r][1] + bsv[1];
        o.z = acc[r][2] + bsv[2];
        o.w = acc[r][3] + bsv[3];
        *(float4*)(C + (size_t)(b0 + ty * 4 + r) * F + i0 + tx * 4) = o;
    }
}

// ---------------- K4: per-action gather GEMM ----------------
// grid (4, NACT), 256 threads. Tile: 16 batch rows x 128 out dims, Kt=16.
// out[b][i] = sum_j W[a][i][j] * p_embed[b][j]
__global__ void k_action(const float* __restrict__ W, float* __restrict__ dout)
{
    const int a  = blockIdx.y;
    const int i0 = blockIdx.x * 128;
    const int beg = g_off[a];
    const int n   = g_off[a + 1] - beg;
    if (n == 0) return;

    __shared__ float Bs[16][128];  // W tile [k][i]
    __shared__ float As[16][16];   // P tile [k][m]

    const int t  = threadIdx.x;    // 0..255
    const int tm = t >> 4;         // batch row within chunk 0..15
    const int tn = t & 15;         // i group: i0 + tn*8 .. +7

    const float* Wa = W + (size_t)a * F * F;

    for (int m0 = 0; m0 < n; m0 += 16) {
        const int mrem = min(16, n - m0);
        float acc[8] = {};

        for (int k0 = 0; k0 < F; k0 += 16) {
            // stage W tile: 128 rows x 16 k = 512 float4, 2 per thread
            #pragma unroll
            for (int q = 0; q < 2; q++) {
                int idx = t + q * 256;       // float4 index 0..511
                int r   = idx >> 2;          // W row 0..127
                int kq  = (idx & 3) * 4;
                float4 wv = *(const float4*)(Wa + (size_t)(i0 + r) * F + k0 + kq);
                Bs[kq + 0][r] = wv.x; Bs[kq + 1][r] = wv.y;
                Bs[kq + 2][r] = wv.z; Bs[kq + 3][r] = wv.w;
            }
            // stage P tile: 16 x 16
            {
                int m  = t >> 4;
                int kk = t & 15;
                float v = 0.f;
                if (m < mrem) {
                    int brow = g_perm[beg + m0 + m];
                    v = g_p_embed[(size_t)brow * F + k0 + kk];
                }
                As[kk][m] = v;
            }
            __syncthreads();

            #pragma unroll
            for (int kk = 0; kk < 16; kk++) {
                float av   = As[kk][tm];
                float4 b0v = *(const float4*)&Bs[kk][tn * 8];
                float4 b1v = *(const float4*)&Bs[kk][tn * 8 + 4];
                acc[0] += av * b0v.x; acc[1] += av * b0v.y;
                acc[2] += av * b0v.z; acc[3] += av * b0v.w;
                acc[4] += av * b1v.x; acc[5] += av * b1v.y;
                acc[6] += av * b1v.z; acc[7] += av * b1v.w;
            }
            __syncthreads();
        }

        if (tm < mrem) {
            int brow = g_perm[beg + m0 + tm];
            float4 o0 = make_float4(acc[0], acc[1], acc[2], acc[3]);
            float4 o1 = make_float4(acc[4], acc[5], acc[6], acc[7]);
            *(float4*)(dout + (size_t)brow * F + i0 + tn * 8)     = o0;
            *(float4*)(dout + (size_t)brow * F + i0 + tn * 8 + 4) = o1;
        }
    }
}

// ---------------- launch ----------------
extern "C" void kernel_launch(void* const* d_in, const int* in_sizes, int n_in,
                              void* d_out, int out_size)
{
    const float* pre   = (const float*)d_in[0];
    const float* eff   = (const float*)d_in[1];
    const int*   act   = (const int*)  d_in[2];
    const float* W     = (const float*)d_in[3];
    const float* pw    = (const float*)d_in[4];
    const float* pb    = (const float*)d_in[5];
    const float* ew    = (const float*)d_in[6];
    const float* eb    = (const float*)d_in[7];
    const float* gamma = (const float*)d_in[8];
    const float* beta  = (const float*)d_in[9];
    float* out = (float*)d_out;

    k_reduce_gn<<<dim3(BATCH, 2), 128>>>(pre, eff, gamma, beta);
    k_group<<<1, 256>>>(act);
    k_embed<<<dim3(F / 64, BATCH / 64, 2), 256>>>(pw, pb, ew, eb, out);
    k_action<<<dim3(4, NACT), 256>>>(W, out);
}

// round 3
// speedup vs baseline: 1.3493x; 1.3493x over previous
#include <cuda_runtime.h>

#define BATCH 2048
#define SEQ   128
#define F     512
#define NACT  128
#define GN_EPS 1e-5f

// ---------------- scratch (no allocations allowed) ----------------
__device__ float g_p_avg[BATCH * F];
__device__ float g_e_avg[BATCH * F];
__device__ float g_p_embed[BATCH * F];
__device__ int   g_off[NACT + 1];
__device__ int   g_perm[BATCH];

// ---------------- K1: masked mean over seq + GroupNorm(1,1) ----------------
// grid (2048, 2), 128 threads. blockIdx.y: 0 -> precondition, 1 -> effect.
__global__ void k_reduce_gn(const float* __restrict__ pre,
                            const float* __restrict__ eff,
                            const float* __restrict__ gamma,
                            const float* __restrict__ beta)
{
    const int b = blockIdx.x;
    const float* src = (blockIdx.y == 0) ? pre : eff;
    float* dst       = (blockIdx.y == 0) ? g_p_avg : g_e_avg;

    const int t = threadIdx.x;  // 0..127, features 4t..4t+3
    const float4* row = (const float4*)(src + (size_t)b * SEQ * F);

    float4 sum = make_float4(0.f, 0.f, 0.f, 0.f);
    int cx = 0, cy = 0, cz = 0, cw = 0;

    #pragma unroll 8
    for (int s = 0; s < SEQ; s++) {
        float4 v = row[s * (F / 4) + t];
        sum.x += v.x; sum.y += v.y; sum.z += v.z; sum.w += v.w;
        cx += (v.x != 0.0f); cy += (v.y != 0.0f);
        cz += (v.z != 0.0f); cw += (v.w != 0.0f);
    }

    float4 m;
    m.x = sum.x / (float)cx;
    m.y = sum.y / (float)cy;
    m.z = sum.z / (float)cz;
    m.w = sum.w / (float)cw;

    float ls = m.x + m.y + m.z + m.w;
    float lq = m.x * m.x + m.y * m.y + m.z * m.z + m.w * m.w;

    __shared__ float s1[128], s2[128];
    s1[t] = ls; s2[t] = lq;
    __syncthreads();
    #pragma unroll
    for (int o = 64; o > 0; o >>= 1) {
        if (t < o) { s1[t] += s1[t + o]; s2[t] += s2[t + o]; }
        __syncthreads();
    }
    const float mu  = s1[0] * (1.0f / F);
    const float var = s2[0] * (1.0f / F) - mu * mu;
    const float r   = rsqrtf(var + GN_EPS) * gamma[0];
    const float be  = beta[0];

    float4 o4;
    o4.x = (m.x - mu) * r + be;
    o4.y = (m.y - mu) * r + be;
    o4.z = (m.z - mu) * r + be;
    o4.w = (m.w - mu) * r + be;
    ((float4*)(dst + (size_t)b * F))[t] = o4;
}

// ---------------- K2: group batch indices by action ----------------
__global__ void k_group(const int* __restrict__ action)
{
    __shared__ int s_cnt[NACT];
    __shared__ int s_cur[NACT];
    const int t = threadIdx.x;
    if (t < NACT) s_cnt[t] = 0;
    __syncthreads();
    for (int i = t; i < BATCH; i += 256)
        atomicAdd(&s_cnt[action[i]], 1);
    __syncthreads();
    if (t == 0) {
        int acc = 0;
        for (int a = 0; a < NACT; a++) {
            g_off[a] = acc; s_cur[a] = acc; acc += s_cnt[a];
        }
        g_off[NACT] = acc;
    }
    __syncthreads();
    for (int i = t; i < BATCH; i += 256) {
        int pos = atomicAdd(&s_cur[action[i]], 1);
        g_perm[pos] = i;
    }
}

// ---------------- K3: embed GEMMs ----------------
// C[b][i] = dot(A[b,:], Wt[i,:]) + bias[i]
// grid (F/64, BATCH/128, 2), 256 threads. Tile 128m x 64i, Kt=16,
// 8x4 microtile, register double-buffered staging.
__global__ void __launch_bounds__(256)
k_embed(const float* __restrict__ pw, const float* __restrict__ pb,
        const float* __restrict__ ew, const float* __restrict__ eb,
        float* __restrict__ dout)
{
    const float* A; const float* Wt; const float* bias; float* C;
    if (blockIdx.z == 0) { A = g_p_avg; Wt = pw; bias = pb; C = g_p_embed; }
    else                 { A = g_e_avg; Wt = ew; bias = eb; C = dout + (size_t)BATCH * F; }

    const int i0 = blockIdx.x * 64;
    const int b0 = blockIdx.y * 128;

    __shared__ float As[16][128];   // [k][m]
    __shared__ float Bs[16][64];    // [k][i]

    const int t  = threadIdx.x;      // 0..255
    const int tx = t & 15;           // i micro: 4 cols at tx*4
    const int ty = t >> 4;           // m micro: 8 rows at ty*8

    const int lr = t >> 2;           // loader row 0..63
    const int lk = (t & 3) * 4;      // loader k offset

    float acc[8][4];
    #pragma unroll
    for (int r = 0; r < 8; r++)
        #pragma unroll
        for (int c = 0; c < 4; c++) acc[r][c] = 0.f;

    // prefetch chunk 0
    float4 a0 = *(const float4*)(A  + (size_t)(b0 + lr)      * F + lk);
    float4 a1 = *(const float4*)(A  + (size_t)(b0 + lr + 64) * F + lk);
    float4 bv = *(const float4*)(Wt + (size_t)(i0 + lr)      * F + lk);

    for (int k0 = 0; k0 < F; k0 += 16) {
        As[lk + 0][lr]      = a0.x; As[lk + 1][lr]      = a0.y;
        As[lk + 2][lr]      = a0.z; As[lk + 3][lr]      = a0.w;
        As[lk + 0][lr + 64] = a1.x; As[lk + 1][lr + 64] = a1.y;
        As[lk + 2][lr + 64] = a1.z; As[lk + 3][lr + 64] = a1.w;
        Bs[lk + 0][lr] = bv.x; Bs[lk + 1][lr] = bv.y;
        Bs[lk + 2][lr] = bv.z; Bs[lk + 3][lr] = bv.w;
        __syncthreads();

        if (k0 + 16 < F) {
            a0 = *(const float4*)(A  + (size_t)(b0 + lr)      * F + k0 + 16 + lk);
            a1 = *(const float4*)(A  + (size_t)(b0 + lr + 64) * F + k0 + 16 + lk);
            bv = *(const float4*)(Wt + (size_t)(i0 + lr)      * F + k0 + 16 + lk);
        }

        #pragma unroll
        for (int kk = 0; kk < 16; kk++) {
            float4 ra0 = *(const float4*)&As[kk][ty * 8];
            float4 ra1 = *(const float4*)&As[kk][ty * 8 + 4];
            float4 rb  = *(const float4*)&Bs[kk][tx * 4];
            float am[8] = { ra0.x, ra0.y, ra0.z, ra0.w, ra1.x, ra1.y, ra1.z, ra1.w };
            float bn[4] = { rb.x, rb.y, rb.z, rb.w };
            #pragma unroll
            for (int r = 0; r < 8; r++)
                #pragma unroll
                for (int c = 0; c < 4; c++)
                    acc[r][c] += am[r] * bn[c];
        }
        __syncthreads();
    }

    float bsv[4];
    #pragma unroll
    for (int c = 0; c < 4; c++) bsv[c] = bias[i0 + tx * 4 + c];

    #pragma unroll
    for (int r = 0; r < 8; r++) {
        float4 o;
        o.x = acc[r][0] + bsv[0];
        o.y = acc[r][1] + bsv[1];
        o.z = acc[r][2] + bsv[2];
        o.w = acc[r][3] + bsv[3];
        *(float4*)(C + (size_t)(b0 + ty * 8 + r) * F + i0 + tx * 4) = o;
    }
}

// ---------------- K4: per-action gather GEMM ----------------
// out[b][i] = sum_j W[a][i][j] * p_embed[b][j]
// grid (4, NACT, 2), 256 threads. Tile 128i x 16m, Kt=16,
// z-split over m-chunks, register double-buffered W/P staging.
__global__ void __launch_bounds__(256)
k_action(const float* __restrict__ W, float* __restrict__ dout)
{
    const int a   = blockIdx.y;
    const int i0  = blockIdx.x * 128;
    const int beg = g_off[a];
    const int n   = g_off[a + 1] - beg;
    const int m0s = blockIdx.z * 16;
    if (m0s >= n) return;

    __shared__ float Bs[16][128];   // W tile [k][i]
    __shared__ float As[16][16];    // P tile [k][m]
    __shared__ int   rows[16];

    const int t  = threadIdx.x;     // 0..255
    const int tm = t >> 4;          // 0..15 (m row)
    const int tn = t & 15;          // i group: i0 + tn*8 .. +7

    const int lr = t >> 2;          // W loader row 0..63
    const int lk = (t & 3) * 4;     // loader k offset

    const int pm = t >> 2;          // P loader m row (t<64)

    const float* Wa = W + (size_t)a * F * F;

    for (int m0 = m0s; m0 < n; m0 += 32) {
        const int mrem = min(16, n - m0);
        __syncthreads();
        if (t < 16) rows[t] = (t < mrem) ? g_perm[beg + m0 + t] : -1;
        __syncthreads();

        float acc[8];
        #pragma unroll
        for (int q = 0; q < 8; q++) acc[q] = 0.f;

        // prefetch chunk 0
        float4 wv0 = *(const float4*)(Wa + (size_t)(i0 + lr)      * F + lk);
        float4 wv1 = *(const float4*)(Wa + (size_t)(i0 + lr + 64) * F + lk);
        float4 pv  = make_float4(0.f, 0.f, 0.f, 0.f);
        if (t < 64) {
            int brow = rows[pm];
            if (brow >= 0)
                pv = *(const float4*)(g_p_embed + (size_t)brow * F + lk);
        }

        for (int k0 = 0; k0 < F; k0 += 16) {
            Bs[lk + 0][lr]      = wv0.x; Bs[lk + 1][lr]      = wv0.y;
            Bs[lk + 2][lr]      = wv0.z; Bs[lk + 3][lr]      = wv0.w;
            Bs[lk + 0][lr + 64] = wv1.x; Bs[lk + 1][lr + 64] = wv1.y;
            Bs[lk + 2][lr + 64] = wv1.z; Bs[lk + 3][lr + 64] = wv1.w;
            if (t < 64) {
                As[lk + 0][pm] = pv.x; As[lk + 1][pm] = pv.y;
                As[lk + 2][pm] = pv.z; As[lk + 3][pm] = pv.w;
            }
            __syncthreads();

            if (k0 + 16 < F) {
                wv0 = *(const float4*)(Wa + (size_t)(i0 + lr)      * F + k0 + 16 + lk);
                wv1 = *(const float4*)(Wa + (size_t)(i0 + lr + 64) * F + k0 + 16 + lk);
                if (t < 64) {
                    int brow = rows[pm];
                    if (brow >= 0)
                        pv = *(const float4*)(g_p_embed + (size_t)brow * F + k0 + 16 + lk);
                }
            }

            #pragma unroll
            for (int kk = 0; kk < 16; kk++) {
                float  av  = As[kk][tm];
                float4 b0v = *(const float4*)&Bs[kk][tn * 8];
                float4 b1v = *(const float4*)&Bs[kk][tn * 8 + 4];
                acc[0] += av * b0v.x; acc[1] += av * b0v.y;
                acc[2] += av * b0v.z; acc[3] += av * b0v.w;
                acc[4] += av * b1v.x; acc[5] += av * b1v.y;
                acc[6] += av * b1v.z; acc[7] += av * b1v.w;
            }
            __syncthreads();
        }

        int orow = rows[tm];
        if (orow >= 0) {
            float4 o0 = make_float4(acc[0], acc[1], acc[2], acc[3]);
            float4 o1 = make_float4(acc[4], acc[5], acc[6], acc[7]);
            *(float4*)(dout + (size_t)orow * F + i0 + tn * 8)     = o0;
            *(float4*)(dout + (size_t)orow * F + i0 + tn * 8 + 4) = o1;
        }
    }
}

// ---------------- launch ----------------
extern "C" void kernel_launch(void* const* d_in, const int* in_sizes, int n_in,
                              void* d_out, int out_size)
{
    const float* pre   = (const float*)d_in[0];
    const float* eff   = (const float*)d_in[1];
    const int*   act   = (const int*)  d_in[2];
    const float* W     = (const float*)d_in[3];
    const float* pw    = (const float*)d_in[4];
    const float* pb    = (const float*)d_in[5];
    const float* ew    = (const float*)d_in[6];
    const float* eb    = (const float*)d_in[7];
    const float* gamma = (const float*)d_in[8];
    const float* beta  = (const float*)d_in[9];
    float* out = (float*)d_out;

    k_reduce_gn<<<dim3(BATCH, 2), 128>>>(pre, eff, gamma, beta);
    k_group<<<1, 256>>>(act);
    k_embed<<<dim3(F / 64, BATCH / 128, 2), 256>>>(pw, pb, ew, eb, out);
    k_action<<<dim3(4, NACT, 2), 256>>>(W, out);
}

// round 5
// speedup vs baseline: 1.4816x; 1.0981x over previous
#include <cuda_runtime.h>

#define BATCH 2048
#define SEQ   128
#define F     512
#define NACT  128
#define GN_EPS 1e-5f

// ---------------- scratch (no allocations allowed) ----------------
__device__ float g_p_avg[BATCH * F];
__device__ float g_e_avg[BATCH * F];
__device__ float g_p_embed[BATCH * F];
__device__ int   g_off[NACT + 1];
__device__ int   g_perm[BATCH];

// ---------------- K1: masked mean over seq + GroupNorm(1,1) ----------------
__global__ void k_reduce_gn(const float* __restrict__ pre,
                            const float* __restrict__ eff,
                            const float* __restrict__ gamma,
                            const float* __restrict__ beta)
{
    const int b = blockIdx.x;
    const float* src = (blockIdx.y == 0) ? pre : eff;
    float* dst       = (blockIdx.y == 0) ? g_p_avg : g_e_avg;

    const int t = threadIdx.x;  // 0..127
    const float4* row = (const float4*)(src + (size_t)b * SEQ * F);

    float4 sum = make_float4(0.f, 0.f, 0.f, 0.f);
    int cx = 0, cy = 0, cz = 0, cw = 0;

    #pragma unroll 8
    for (int s = 0; s < SEQ; s++) {
        float4 v = row[s * (F / 4) + t];
        sum.x += v.x; sum.y += v.y; sum.z += v.z; sum.w += v.w;
        cx += (v.x != 0.0f); cy += (v.y != 0.0f);
        cz += (v.z != 0.0f); cw += (v.w != 0.0f);
    }

    float4 m;
    m.x = sum.x / (float)cx;
    m.y = sum.y / (float)cy;
    m.z = sum.z / (float)cz;
    m.w = sum.w / (float)cw;

    float ls = m.x + m.y + m.z + m.w;
    float lq = m.x * m.x + m.y * m.y + m.z * m.z + m.w * m.w;

    __shared__ float s1[128], s2[128];
    s1[t] = ls; s2[t] = lq;
    __syncthreads();
    #pragma unroll
    for (int o = 64; o > 0; o >>= 1) {
        if (t < o) { s1[t] += s1[t + o]; s2[t] += s2[t + o]; }
        __syncthreads();
    }
    const float mu  = s1[0] * (1.0f / F);
    const float var = s2[0] * (1.0f / F) - mu * mu;
    const float r   = rsqrtf(var + GN_EPS) * gamma[0];
    const float be  = beta[0];

    float4 o4;
    o4.x = (m.x - mu) * r + be;
    o4.y = (m.y - mu) * r + be;
    o4.z = (m.z - mu) * r + be;
    o4.w = (m.w - mu) * r + be;
    ((float4*)(dst + (size_t)b * F))[t] = o4;
}

// ---------------- K2: group batch indices by action ----------------
__global__ void k_group(const int* __restrict__ action)
{
    __shared__ int s_cnt[NACT];
    __shared__ int s_cur[NACT];
    const int t = threadIdx.x;
    if (t < NACT) s_cnt[t] = 0;
    __syncthreads();
    for (int i = t; i < BATCH; i += 256)
        atomicAdd(&s_cnt[action[i]], 1);
    __syncthreads();
    if (t == 0) {
        int acc = 0;
        for (int a = 0; a < NACT; a++) {
            g_off[a] = acc; s_cur[a] = acc; acc += s_cnt[a];
        }
        g_off[NACT] = acc;
    }
    __syncthreads();
    for (int i = t; i < BATCH; i += 256) {
        int pos = atomicAdd(&s_cur[action[i]], 1);
        g_perm[pos] = i;
    }
}

// ---------------- K3: embed GEMMs ----------------
// grid (F/64, BATCH/128, 2), 256 threads. Tile 128m x 64i, Kt=16, 8x4 microtile.
__global__ void __launch_bounds__(256)
k_embed(const float* __restrict__ pw, const float* __restrict__ pb,
        const float* __restrict__ ew, const float* __restrict__ eb,
        float* __restrict__ dout)
{
    const float* A; const float* Wt; const float* bias; float* C;
    if (blockIdx.z == 0) { A = g_p_avg; Wt = pw; bias = pb; C = g_p_embed; }
    else                 { A = g_e_avg; Wt = ew; bias = eb; C = dout + (size_t)BATCH * F; }

    const int i0 = blockIdx.x * 64;
    const int b0 = blockIdx.y * 128;

    __shared__ float As[16][128];
    __shared__ float Bs[16][64];

    const int t  = threadIdx.x;
    const int tx = t & 15;
    const int ty = t >> 4;

    const int lr = t >> 2;
    const int lk = (t & 3) * 4;

    float acc[8][4];
    #pragma unroll
    for (int r = 0; r < 8; r++)
        #pragma unroll
        for (int c = 0; c < 4; c++) acc[r][c] = 0.f;

    float4 a0 = *(const float4*)(A  + (size_t)(b0 + lr)      * F + lk);
    float4 a1 = *(const float4*)(A  + (size_t)(b0 + lr + 64) * F + lk);
    float4 bv = *(const float4*)(Wt + (size_t)(i0 + lr)      * F + lk);

    for (int k0 = 0; k0 < F; k0 += 16) {
        As[lk + 0][lr]      = a0.x; As[lk + 1][lr]      = a0.y;
        As[lk + 2][lr]      = a0.z; As[lk + 3][lr]      = a0.w;
        As[lk + 0][lr + 64] = a1.x; As[lk + 1][lr + 64] = a1.y;
        As[lk + 2][lr + 64] = a1.z; As[lk + 3][lr + 64] = a1.w;
        Bs[lk + 0][lr] = bv.x; Bs[lk + 1][lr] = bv.y;
        Bs[lk + 2][lr] = bv.z; Bs[lk + 3][lr] = bv.w;
        __syncthreads();

        if (k0 + 16 < F) {
            a0 = *(const float4*)(A  + (size_t)(b0 + lr)      * F + k0 + 16 + lk);
            a1 = *(const float4*)(A  + (size_t)(b0 + lr + 64) * F + k0 + 16 + lk);
            bv = *(const float4*)(Wt + (size_t)(i0 + lr)      * F + k0 + 16 + lk);
        }

        #pragma unroll
        for (int kk = 0; kk < 16; kk++) {
            float4 ra0 = *(const float4*)&As[kk][ty * 8];
            float4 ra1 = *(const float4*)&As[kk][ty * 8 + 4];
            float4 rb  = *(const float4*)&Bs[kk][tx * 4];
            float am[8] = { ra0.x, ra0.y, ra0.z, ra0.w, ra1.x, ra1.y, ra1.z, ra1.w };
            float bn[4] = { rb.x, rb.y, rb.z, rb.w };
            #pragma unroll
            for (int r = 0; r < 8; r++)
                #pragma unroll
                for (int c = 0; c < 4; c++)
                    acc[r][c] += am[r] * bn[c];
        }
        __syncthreads();
    }

    float bsv[4];
    #pragma unroll
    for (int c = 0; c < 4; c++) bsv[c] = bias[i0 + tx * 4 + c];

    #pragma unroll
    for (int r = 0; r < 8; r++) {
        float4 o;
        o.x = acc[r][0] + bsv[0];
        o.y = acc[r][1] + bsv[1];
        o.z = acc[r][2] + bsv[2];
        o.w = acc[r][3] + bsv[3];
        *(float4*)(C + (size_t)(b0 + ty * 8 + r) * F + i0 + tx * 4) = o;
    }
}

// ---------------- K4: per-action gather GEMM ----------------
// out[b][i] = sum_j W[a][i][j] * p_embed[b][j]
// grid (NACT, 2), 256 threads. CTA tile 512i x 16m. Thread micro-tile 8i x 4m.
// P^T staged once per m-chunk; W streamed via Bs[8][512] with reg prefetch.
__global__ void __launch_bounds__(256)
k_action(const float* __restrict__ W, float* __restrict__ dout)
{
    const int a   = blockIdx.x;
    const int z   = blockIdx.y;
    const int beg = g_off[a];
    const int n   = g_off[a + 1] - beg;
    if (z * 16 >= n) return;

    __shared__ float As[F][16];     // P^T  [k][m]   32 KB
    __shared__ float Bs[8][F];      // W    [k][i]   16 KB

    const int t  = threadIdx.x;     // 0..255
    const int mg = t >> 6;          // 0..3   (m rows mg*4..+3)
    const int tn = t & 63;          // 0..63  (i cols tn*8..+7)

    const float* Wa = W + (size_t)a * F * F;
    const int r0 = t << 1;          // W staging rows r0, r0+1

    for (int m0 = z * 16; m0 < n; m0 += 32) {
        // ---- stage P^T: 16 rows x 512, transposed ----
        {
            const int m  = t >> 4;          // 0..15
            const int c0 = t & 15;          // f4 column base
            // rows past n read a valid row (clamped) but are never written out
            const int mi   = (m0 + m < n) ? (m0 + m) : m0;
            const float* src = g_p_embed + (size_t)g_perm[beg + mi] * F;
            #pragma unroll
            for (int j = 0; j < 8; j++) {
                int kf = (c0 + j * 16) * 4;
                float4 v = *(const float4*)(src + kf);
                As[kf + 0][m] = v.x; As[kf + 1][m] = v.y;
                As[kf + 2][m] = v.z; As[kf + 3][m] = v.w;
            }
        }

        float acc[4][8];
        #pragma unroll
        for (int r = 0; r < 4; r++)
            #pragma unroll
            for (int c = 0; c < 8; c++) acc[r][c] = 0.f;

        // prefetch W chunk 0
        float4 w00 = *(const float4*)(Wa + (size_t)r0       * F + 0);
        float4 w01 = *(const float4*)(Wa + (size_t)r0       * F + 4);
        float4 w10 = *(const float4*)(Wa + (size_t)(r0 + 1) * F + 0);
        float4 w11 = *(const float4*)(Wa + (size_t)(r0 + 1) * F + 4);
        __syncthreads();   // As ready, Bs free

        for (int c = 0; c < F / 8; c++) {
            // store staged W chunk (transposed)
            Bs[0][r0] = w00.x; Bs[1][r0] = w00.y; Bs[2][r0] = w00.z; Bs[3][r0] = w00.w;
            Bs[4][r0] = w01.x; Bs[5][r0] = w01.y; Bs[6][r0] = w01.z; Bs[7][r0] = w01.w;
            Bs[0][r0+1] = w10.x; Bs[1][r0+1] = w10.y; Bs[2][r0+1] = w10.z; Bs[3][r0+1] = w10.w;
            Bs[4][r0+1] = w11.x; Bs[5][r0+1] = w11.y; Bs[6][r0+1] = w11.z; Bs[7][r0+1] = w11.w;
            __syncthreads();

            if (c + 1 < F / 8) {
                int kn = (c + 1) * 8;
                w00 = *(const float4*)(Wa + (size_t)r0       * F + kn);
                w01 = *(const float4*)(Wa + (size_t)r0       * F + kn + 4);
                w10 = *(const float4*)(Wa + (size_t)(r0 + 1) * F + kn);
                w11 = *(const float4*)(Wa + (size_t)(r0 + 1) * F + kn + 4);
            }

            const int kb = c * 8;
            #pragma unroll
            for (int kk = 0; kk < 8; kk++) {
                float4 am = *(const float4*)&As[kb + kk][mg * 4];   // broadcast
                float4 b0 = *(const float4*)&Bs[kk][tn * 8];
                float4 b1 = *(const float4*)&Bs[kk][tn * 8 + 4];
                float av[4] = { am.x, am.y, am.z, am.w };
                float bv[8] = { b0.x, b0.y, b0.z, b0.w, b1.x, b1.y, b1.z, b1.w };
                #pragma unroll
                for (int r = 0; r < 4; r++)
                    #pragma unroll
                    for (int cc = 0; cc < 8; cc++)
                        acc[r][cc] += av[r] * bv[cc];
            }
            __syncthreads();
        }

        // write out
        #pragma unroll
        for (int mi2 = 0; mi2 < 4; mi2++) {
            int m = mg * 4 + mi2;
            if (m0 + m < n) {
                int orow = g_perm[beg + m0 + m];
                float4 o0 = make_float4(acc[mi2][0], acc[mi2][1], acc[mi2][2], acc[mi2][3]);
                float4 o1 = make_float4(acc[mi2][4], acc[mi2][5], acc[mi2][6], acc[mi2][7]);
                *(float4*)(dout + (size_t)orow * F + tn * 8)     = o0;
                *(float4*)(dout + (size_t)orow * F + tn * 8 + 4) = o1;
            }
        }
        __syncthreads();   // protect As before next m-chunk restages it
    }
}

// ---------------- launch ----------------
extern "C" void kernel_launch(void* const* d_in, const int* in_sizes, int n_in,
                              void* d_out, int out_size)
{
    const float* pre   = (const float*)d_in[0];
    const float* eff   = (const float*)d_in[1];
    const int*   act   = (const int*)  d_in[2];
    const float* W     = (const float*)d_in[3];
    const float* pw    = (const float*)d_in[4];
    const float* pb    = (const float*)d_in[5];
    const float* ew    = (const float*)d_in[6];
    const float* eb    = (const float*)d_in[7];
    const float* gamma = (const float*)d_in[8];
    const float* beta  = (const float*)d_in[9];
    float* out = (float*)d_out;

    k_reduce_gn<<<dim3(BATCH, 2), 128>>>(pre, eff, gamma, beta);
    k_group<<<1, 256>>>(act);
    k_embed<<<dim3(F / 64, BATCH / 128, 2), 256>>>(pw, pb, ew, eb, out);
    k_action<<<dim3(NACT, 2), 256>>>(W, out);
}

// round 6
// speedup vs baseline: 1.5449x; 1.0427x over previous
#include <cuda_runtime.h>

#define BATCH 2048
#define SEQ   128
#define F     512
#define NACT  128
#define GN_EPS 1e-5f

// ---------------- scratch (no allocations allowed) ----------------
__device__ float g_p_avg[BATCH * F];
__device__ float g_e_avg[BATCH * F];
__device__ float g_p_embed[BATCH * F];
__device__ int   g_off[NACT + 1];
__device__ int   g_perm[BATCH];

// ---------------- K1: masked mean over seq + GroupNorm(1,1) ----------------
__global__ void k_reduce_gn(const float* __restrict__ pre,
                            const float* __restrict__ eff,
                            const float* __restrict__ gamma,
                            const float* __restrict__ beta)
{
    const int b = blockIdx.x;
    const float* src = (blockIdx.y == 0) ? pre : eff;
    float* dst       = (blockIdx.y == 0) ? g_p_avg : g_e_avg;

    const int t = threadIdx.x;  // 0..127
    const float4* row = (const float4*)(src + (size_t)b * SEQ * F);

    float4 sum = make_float4(0.f, 0.f, 0.f, 0.f);
    int cx = 0, cy = 0, cz = 0, cw = 0;

    #pragma unroll 8
    for (int s = 0; s < SEQ; s++) {
        float4 v = row[s * (F / 4) + t];
        sum.x += v.x; sum.y += v.y; sum.z += v.z; sum.w += v.w;
        cx += (v.x != 0.0f); cy += (v.y != 0.0f);
        cz += (v.z != 0.0f); cw += (v.w != 0.0f);
    }

    float4 m;
    m.x = sum.x / (float)cx;
    m.y = sum.y / (float)cy;
    m.z = sum.z / (float)cz;
    m.w = sum.w / (float)cw;

    float ls = m.x + m.y + m.z + m.w;
    float lq = m.x * m.x + m.y * m.y + m.z * m.z + m.w * m.w;

    __shared__ float s1[128], s2[128];
    s1[t] = ls; s2[t] = lq;
    __syncthreads();
    #pragma unroll
    for (int o = 64; o > 0; o >>= 1) {
        if (t < o) { s1[t] += s1[t + o]; s2[t] += s2[t + o]; }
        __syncthreads();
    }
    const float mu  = s1[0] * (1.0f / F);
    const float var = s2[0] * (1.0f / F) - mu * mu;
    const float r   = rsqrtf(var + GN_EPS) * gamma[0];
    const float be  = beta[0];

    float4 o4;
    o4.x = (m.x - mu) * r + be;
    o4.y = (m.y - mu) * r + be;
    o4.z = (m.z - mu) * r + be;
    o4.w = (m.w - mu) * r + be;
    ((float4*)(dst + (size_t)b * F))[t] = o4;
}

// ---------------- K2: group batch indices by action ----------------
__global__ void k_group(const int* __restrict__ action)
{
    __shared__ int s_cnt[NACT];
    __shared__ int s_cur[NACT];
    const int t = threadIdx.x;
    if (t < NACT) s_cnt[t] = 0;
    __syncthreads();
    for (int i = t; i < BATCH; i += 256)
        atomicAdd(&s_cnt[action[i]], 1);
    __syncthreads();
    if (t == 0) {
        int acc = 0;
        for (int a = 0; a < NACT; a++) {
            g_off[a] = acc; s_cur[a] = acc; acc += s_cnt[a];
        }
        g_off[NACT] = acc;
    }
    __syncthreads();
    for (int i = t; i < BATCH; i += 256) {
        int pos = atomicAdd(&s_cur[action[i]], 1);
        g_perm[pos] = i;
    }
}

// ---------------- K3: embed GEMMs ----------------
// grid (F/64, BATCH/128, 2), 256 threads. Tile 128m x 64i, Kt=16, 8x4 microtile.
__global__ void __launch_bounds__(256)
k_embed(const float* __restrict__ pw, const float* __restrict__ pb,
        const float* __restrict__ ew, const float* __restrict__ eb,
        float* __restrict__ dout)
{
    const float* A; const float* Wt; const float* bias; float* C;
    if (blockIdx.z == 0) { A = g_p_avg; Wt = pw; bias = pb; C = g_p_embed; }
    else                 { A = g_e_avg; Wt = ew; bias = eb; C = dout + (size_t)BATCH * F; }

    const int i0 = blockIdx.x * 64;
    const int b0 = blockIdx.y * 128;

    __shared__ float As[16][128];
    __shared__ float Bs[16][64];

    const int t  = threadIdx.x;
    const int tx = t & 15;
    const int ty = t >> 4;

    const int lr = t >> 2;
    const int lk = (t & 3) * 4;

    float acc[8][4];
    #pragma unroll
    for (int r = 0; r < 8; r++)
        #pragma unroll
        for (int c = 0; c < 4; c++) acc[r][c] = 0.f;

    float4 a0 = *(const float4*)(A  + (size_t)(b0 + lr)      * F + lk);
    float4 a1 = *(const float4*)(A  + (size_t)(b0 + lr + 64) * F + lk);
    float4 bv = *(const float4*)(Wt + (size_t)(i0 + lr)      * F + lk);

    for (int k0 = 0; k0 < F; k0 += 16) {
        As[lk + 0][lr]      = a0.x; As[lk + 1][lr]      = a0.y;
        As[lk + 2][lr]      = a0.z; As[lk + 3][lr]      = a0.w;
        As[lk + 0][lr + 64] = a1.x; As[lk + 1][lr + 64] = a1.y;
        As[lk + 2][lr + 64] = a1.z; As[lk + 3][lr + 64] = a1.w;
        Bs[lk + 0][lr] = bv.x; Bs[lk + 1][lr] = bv.y;
        Bs[lk + 2][lr] = bv.z; Bs[lk + 3][lr] = bv.w;
        __syncthreads();

        if (k0 + 16 < F) {
            a0 = *(const float4*)(A  + (size_t)(b0 + lr)      * F + k0 + 16 + lk);
            a1 = *(const float4*)(A  + (size_t)(b0 + lr + 64) * F + k0 + 16 + lk);
            bv = *(const float4*)(Wt + (size_t)(i0 + lr)      * F + k0 + 16 + lk);
        }

        #pragma unroll
        for (int kk = 0; kk < 16; kk++) {
            float4 ra0 = *(const float4*)&As[kk][ty * 8];
            float4 ra1 = *(const float4*)&As[kk][ty * 8 + 4];
            float4 rb  = *(const float4*)&Bs[kk][tx * 4];
            float am[8] = { ra0.x, ra0.y, ra0.z, ra0.w, ra1.x, ra1.y, ra1.z, ra1.w };
            float bn[4] = { rb.x, rb.y, rb.z, rb.w };
            #pragma unroll
            for (int r = 0; r < 8; r++)
                #pragma unroll
                for (int c = 0; c < 4; c++)
                    acc[r][c] += am[r] * bn[c];
        }
        __syncthreads();
    }

    float bsv[4];
    #pragma unroll
    for (int c = 0; c < 4; c++) bsv[c] = bias[i0 + tx * 4 + c];

    #pragma unroll
    for (int r = 0; r < 8; r++) {
        float4 o;
        o.x = acc[r][0] + bsv[0];
        o.y = acc[r][1] + bsv[1];
        o.z = acc[r][2] + bsv[2];
        o.w = acc[r][3] + bsv[3];
        *(float4*)(C + (size_t)(b0 + ty * 8 + r) * F + i0 + tx * 4) = o;
    }
}

// ---------------- K4: per-action gather GEMM ----------------
// out[b][i] = sum_j W[a][i][j] * p_embed[b][j]
// grid (NACT, 2, 2), 128 threads. CTA tile 256i x 16m, micro-tile 4m x 8i.
// As: P rows row-major (padded); Bs: W 8k-chunk streamed with reg prefetch.
#define FP (F + 4)   // padded As row stride (floats)
__global__ void __launch_bounds__(128)
k_action(const float* __restrict__ W, float* __restrict__ dout)
{
    const int a   = blockIdx.x;
    const int z   = blockIdx.y;       // 0..1  (m-chunk phase)
    const int ih  = blockIdx.z;       // 0..1  (i half)
    const int i0  = ih * 256;
    const int beg = g_off[a];
    const int n   = g_off[a + 1] - beg;
    if (z * 16 >= n) return;

    __shared__ float As[16][FP];      // P rows [m][k]   ~33 KB
    __shared__ float Bs[8][256];      // W chunk [k][i]   8 KB

    const int t  = threadIdx.x;       // 0..127
    const int ti = t & 31;            // i-group: 8 cols at ti*8
    const int tm = t >> 5;            // m-group: 4 rows at tm*4

    const float* Wa = W + (size_t)a * F * F + (size_t)i0 * F;

    for (int m0 = z * 16; m0 < n; m0 += 32) {
        // ---- stage P rows: 16 x 512, row-major ----
        {
            const int m  = t >> 3;            // 0..15
            const int c  = t & 7;             // float4 lane within row
            const int mi = (m0 + m < n) ? (m0 + m) : m0;   // clamp (never written out)
            const float4* src = (const float4*)(g_p_embed + (size_t)g_perm[beg + mi] * F);
            float4* dstr = (float4*)&As[m][0];
            #pragma unroll
            for (int j = 0; j < 16; j++)
                dstr[c + j * 8] = src[c + j * 8];
        }

        float acc[4][8];
        #pragma unroll
        for (int r = 0; r < 4; r++)
            #pragma unroll
            for (int cc = 0; cc < 8; cc++) acc[r][cc] = 0.f;

        // prefetch W chunk 0: rows t and t+128, k 0..7
        float4 w00 = *(const float4*)(Wa + (size_t)t         * F + 0);
        float4 w01 = *(const float4*)(Wa + (size_t)t         * F + 4);
        float4 w10 = *(const float4*)(Wa + (size_t)(t + 128) * F + 0);
        float4 w11 = *(const float4*)(Wa + (size_t)(t + 128) * F + 4);
        __syncthreads();   // As staged; Bs free

        for (int c = 0; c < F / 8; c++) {
            // store staged W chunk (transposed to [k][i]); lanes contiguous in i
            Bs[0][t] = w00.x; Bs[1][t] = w00.y; Bs[2][t] = w00.z; Bs[3][t] = w00.w;
            Bs[4][t] = w01.x; Bs[5][t] = w01.y; Bs[6][t] = w01.z; Bs[7][t] = w01.w;
            Bs[0][t + 128] = w10.x; Bs[1][t + 128] = w10.y;
            Bs[2][t + 128] = w10.z; Bs[3][t + 128] = w10.w;
            Bs[4][t + 128] = w11.x; Bs[5][t + 128] = w11.y;
            Bs[6][t + 128] = w11.z; Bs[7][t + 128] = w11.w;
            __syncthreads();

            if (c + 1 < F / 8) {
                const int kn = (c + 1) * 8;
                w00 = *(const float4*)(Wa + (size_t)t         * F + kn);
                w01 = *(const float4*)(Wa + (size_t)t         * F + kn + 4);
                w10 = *(const float4*)(Wa + (size_t)(t + 128) * F + kn);
                w11 = *(const float4*)(Wa + (size_t)(t + 128) * F + kn + 4);
            }

            const int kb = c * 8;
            #pragma unroll
            for (int kk = 0; kk < 8; kk++) {
                float4 b0 = *(const float4*)&Bs[kk][ti * 8];
                float4 b1 = *(const float4*)&Bs[kk][ti * 8 + 4];
                #pragma unroll
                for (int r = 0; r < 4; r++) {
                    const float av = As[tm * 4 + r][kb + kk];
                    acc[r][0] += av * b0.x; acc[r][1] += av * b0.y;
                    acc[r][2] += av * b0.z; acc[r][3] += av * b0.w;
                    acc[r][4] += av * b1.x; acc[r][5] += av * b1.y;
                    acc[r][6] += av * b1.z; acc[r][7] += av * b1.w;
                }
            }
            __syncthreads();
        }

        // write out 4 m rows x 8 i cols
        #pragma unroll
        for (int r = 0; r < 4; r++) {
            const int m = tm * 4 + r;
            if (m0 + m < n) {
                const int orow = g_perm[beg + m0 + m];
                float4 o0 = make_float4(acc[r][0], acc[r][1], acc[r][2], acc[r][3]);
                float4 o1 = make_float4(acc[r][4], acc[r][5], acc[r][6], acc[r][7]);
                *(float4*)(dout + (size_t)orow * F + i0 + ti * 8)     = o0;
                *(float4*)(dout + (size_t)orow * F + i0 + ti * 8 + 4) = o1;
            }
        }
        __syncthreads();   // protect As before next m-chunk restages it
    }
}

// ---------------- launch ----------------
extern "C" void kernel_launch(void* const* d_in, const int* in_sizes, int n_in,
                              void* d_out, int out_size)
{
    const float* pre   = (const float*)d_in[0];
    const float* eff   = (const float*)d_in[1];
    const int*   act   = (const int*)  d_in[2];
    const float* W     = (const float*)d_in[3];
    const float* pw    = (const float*)d_in[4];
    const float* pb    = (const float*)d_in[5];
    const float* ew    = (const float*)d_in[6];
    const float* eb    = (const float*)d_in[7];
    const float* gamma = (const float*)d_in[8];
    const float* beta  = (const float*)d_in[9];
    float* out = (float*)d_out;

    k_group<<<1, 256>>>(act);
    k_reduce_gn<<<dim3(BATCH, 2), 128>>>(pre, eff, gamma, beta);
    k_embed<<<dim3(F / 64, BATCH / 128, 2), 256>>>(pw, pb, ew, eb, out);
    k_action<<<dim3(NACT, 2, 2), 128>>>(W, out);
}